// round 15
// baseline (speedup 1.0000x reference)
#include <cuda_runtime.h>
#include <cuda_fp16.h>
#include <math.h>
#include <cstdint>

#define NN 50000
#define NE 300000
#define NPAD (NN + 128)

// ---------------- scratch (device globals; no runtime allocation) ----------
__device__ __half   g_h   [(size_t)NPAD * 512];   // fp16 GAT transform
__device__ float    g_lin [(size_t)NPAD * 256];   // fp32 linear residual
__device__ __half   g_xh  [(size_t)NN * 256];     // fp16 input x
__device__ __half   g_buf0[(size_t)NN * 256];     // fp16 layer outputs
__device__ __half   g_buf1[(size_t)NN * 256];
__device__ float    g_asrc[NN * 4];
__device__ float    g_adst[NN * 4];
__device__ int      g_deg [NN];
__device__ int      g_rowptr[NN + 1];
__device__ int      g_cursor[NN];
__device__ int      g_csrc[NE];                   // CSR-ordered source node ids
__device__ __half   g_wt  [425984];               // transposed fp16 weights

// ---------------- helpers ---------------------------------------------------
__device__ __forceinline__ uint32_t smem_u32(const void* p) {
    uint32_t a;
    asm("{ .reg .u64 t; cvta.to.shared.u64 t, %1; cvt.u32.u64 %0, t; }" : "=r"(a) : "l"(p));
    return a;
}
__device__ __forceinline__ void ldsm_x4(uint32_t& r0, uint32_t& r1, uint32_t& r2,
                                        uint32_t& r3, uint32_t addr) {
    asm volatile("ldmatrix.sync.aligned.m8n8.x4.shared.b16 {%0,%1,%2,%3}, [%4];"
                 : "=r"(r0), "=r"(r1), "=r"(r2), "=r"(r3) : "r"(addr));
}
__device__ __forceinline__ void mma_f16(float* c, uint32_t a0, uint32_t a1,
                                        uint32_t a2, uint32_t a3,
                                        uint32_t b0, uint32_t b1) {
    asm volatile(
        "mma.sync.aligned.m16n8k16.row.col.f32.f16.f16.f32 "
        "{%0,%1,%2,%3}, {%4,%5,%6,%7}, {%8,%9}, {%0,%1,%2,%3};"
        : "+f"(c[0]), "+f"(c[1]), "+f"(c[2]), "+f"(c[3])
        : "r"(a0), "r"(a1), "r"(a2), "r"(a3), "r"(b0), "r"(b1));
}
__device__ __forceinline__ void unpack8(const uint4& u, float* f) {
    float2 p;
    p = __half22float2(*reinterpret_cast<const __half2*>(&u.x)); f[0] = p.x; f[1] = p.y;
    p = __half22float2(*reinterpret_cast<const __half2*>(&u.y)); f[2] = p.x; f[3] = p.y;
    p = __half22float2(*reinterpret_cast<const __half2*>(&u.z)); f[4] = p.x; f[5] = p.y;
    p = __half22float2(*reinterpret_cast<const __half2*>(&u.w)); f[6] = p.x; f[7] = p.y;
}
__device__ __forceinline__ float4 edge_w(float4 sa, float4 ad) {
    float4 v;
    v.x = sa.x + ad.x; v.x = v.x > 0.f ? v.x : 0.2f * v.x;
    v.y = sa.y + ad.y; v.y = v.y > 0.f ? v.y : 0.2f * v.y;
    v.z = sa.z + ad.z; v.z = v.z > 0.f ? v.z : 0.2f * v.z;
    v.w = sa.w + ad.w; v.w = v.w > 0.f ? v.w : 0.2f * v.w;
    v.x = expf(v.x); v.y = expf(v.y); v.z = expf(v.z); v.w = expf(v.w);
    return v;
}

// ---------------- fp16 mma.sync GEMM (round-13, unchanged) ------------------
#define GM_SMEM 65536

__global__ __launch_bounds__(128, 2)
void gemm_mma(const __half* __restrict__ A, const __half* __restrict__ Bt,
              __half* __restrict__ C1, float* __restrict__ C2,
              int M, int split, int ld1, int ld2) {
    extern __shared__ char smc[];
    const int K = 256;
    const int tid = threadIdx.x, lane = tid & 31, warp = tid >> 5;
    const int wm = warp >> 1, wn = warp & 1;
    const int mBase = blockIdx.y * 128;
    const int nBase = blockIdx.x * 128;
    const bool toC1 = (nBase < split);
    const int cBase = toC1 ? nBase : (nBase - split);

    const uint32_t sbase = smem_u32(smc);

    float acc[4][8][4];
#pragma unroll
    for (int i = 0; i < 4; i++)
#pragma unroll
        for (int j = 0; j < 8; j++)
#pragma unroll
            for (int r = 0; r < 4; r++) acc[i][j][r] = 0.f;

    const int rowb = tid >> 3;
    const int unit = tid & 7;
    uint32_t dstOff[8];
#pragma unroll
    for (int l = 0; l < 8; l++) {
        int row = rowb + 16 * l;
        dstOff[l] = (uint32_t)(row * 128 + ((unit ^ (row & 7)) << 4));
    }

    const int g  = lane >> 3, iL = lane & 7;
    const int rA  = wm * 64 + iL + (g & 1) * 8;
    const int kA  = g >> 1;
    const int rB  = wn * 64 + iL + (g >> 1) * 8;
    const int kB  = g & 1;
    const int rA7 = rA & 7, rB7 = rB & 7;

    uint4 aH[8], bH[8];
    const uint4 z4 = make_uint4(0, 0, 0, 0);
#pragma unroll
    for (int l = 0; l < 8; l++) {
        int row = rowb + 16 * l;
        int gr = mBase + row;
        aH[l] = (gr < M) ? *reinterpret_cast<const uint4*>(A + (size_t)gr * K + unit * 8) : z4;
        bH[l] = *reinterpret_cast<const uint4*>(Bt + (size_t)(nBase + row) * K + unit * 8);
    }
#pragma unroll
    for (int l = 0; l < 8; l++) {
        *reinterpret_cast<uint4*>(smc + dstOff[l]) = aH[l];
        *reinterpret_cast<uint4*>(smc + 16384 + dstOff[l]) = bH[l];
    }
    __syncthreads();

    int buf = 0;
    for (int k0 = 64; k0 <= K; k0 += 64) {
        const bool more = (k0 < K);
        if (more) {
#pragma unroll
            for (int l = 0; l < 8; l++) {
                int row = rowb + 16 * l;
                int gr = mBase + row;
                aH[l] = (gr < M) ? *reinterpret_cast<const uint4*>(A + (size_t)gr * K + k0 + unit * 8) : z4;
                bH[l] = *reinterpret_cast<const uint4*>(Bt + (size_t)(nBase + row) * K + k0 + unit * 8);
            }
        }
        {
            const uint32_t aB = sbase + (uint32_t)buf * 32768u;
            const uint32_t bB = aB + 16384u;
#pragma unroll
            for (int kt = 0; kt < 4; kt++) {
                uint32_t a[4][4];
#pragma unroll
                for (int mt = 0; mt < 4; mt++) {
                    uint32_t addr = aB + (uint32_t)(rA + mt * 16) * 128u +
                                    (uint32_t)(((kt * 2 + kA) ^ rA7) << 4);
                    ldsm_x4(a[mt][0], a[mt][1], a[mt][2], a[mt][3], addr);
                }
#pragma unroll
                for (int np = 0; np < 4; np++) {
                    uint32_t b0, b1, b2, b3;
                    uint32_t addr = bB + (uint32_t)(rB + np * 16) * 128u +
                                    (uint32_t)(((kt * 2 + kB) ^ rB7) << 4);
                    ldsm_x4(b0, b1, b2, b3, addr);
#pragma unroll
                    for (int i = 0; i < 4; i++) {
                        mma_f16(acc[i][2 * np],     a[i][0], a[i][1], a[i][2], a[i][3], b0, b1);
                        mma_f16(acc[i][2 * np + 1], a[i][0], a[i][1], a[i][2], a[i][3], b2, b3);
                    }
                }
            }
        }
        if (more) {
            char* As = smc + (buf ^ 1) * 32768;
#pragma unroll
            for (int l = 0; l < 8; l++) {
                *reinterpret_cast<uint4*>(As + dstOff[l]) = aH[l];
                *reinterpret_cast<uint4*>(As + 16384 + dstOff[l]) = bH[l];
            }
            __syncthreads();
            buf ^= 1;
        }
    }

    if (toC1) {
#pragma unroll
        for (int i = 0; i < 4; i++) {
            int r0 = mBase + wm * 64 + i * 16 + (lane >> 2);
#pragma unroll
            for (int j = 0; j < 8; j++) {
                int cc = cBase + wn * 64 + j * 8 + (lane & 3) * 2;
                *reinterpret_cast<__half2*>(C1 + (size_t)r0 * ld1 + cc) =
                    __floats2half2_rn(acc[i][j][0], acc[i][j][1]);
                *reinterpret_cast<__half2*>(C1 + (size_t)(r0 + 8) * ld1 + cc) =
                    __floats2half2_rn(acc[i][j][2], acc[i][j][3]);
            }
        }
    } else {
#pragma unroll
        for (int i = 0; i < 4; i++) {
            int r0 = mBase + wm * 64 + i * 16 + (lane >> 2);
#pragma unroll
            for (int j = 0; j < 8; j++) {
                int cc = cBase + wn * 64 + j * 8 + (lane & 3) * 2;
                *reinterpret_cast<float2*>(C2 + (size_t)r0 * ld2 + cc) =
                    make_float2(acc[i][j][0], acc[i][j][1]);
                *reinterpret_cast<float2*>(C2 + (size_t)(r0 + 8) * ld2 + cc) =
                    make_float2(acc[i][j][2], acc[i][j][3]);
            }
        }
    }
}

// ---------------- converts ---------------------------------------------------
__global__ void cvt_x_kernel(const float* __restrict__ in, __half* __restrict__ out, int n8) {
    int i = blockIdx.x * blockDim.x + threadIdx.x;
    if (i >= n8) return;
    float4 a = reinterpret_cast<const float4*>(in)[i * 2];
    float4 b = reinterpret_cast<const float4*>(in)[i * 2 + 1];
    uint4 r;
    __half2 h;
    h = __floats2half2_rn(a.x, a.y); r.x = *reinterpret_cast<uint32_t*>(&h);
    h = __floats2half2_rn(a.z, a.w); r.y = *reinterpret_cast<uint32_t*>(&h);
    h = __floats2half2_rn(b.x, b.y); r.z = *reinterpret_cast<uint32_t*>(&h);
    h = __floats2half2_rn(b.z, b.w); r.w = *reinterpret_cast<uint32_t*>(&h);
    reinterpret_cast<uint4*>(out)[i] = r;
}

__global__ void transpose_cvt(const float* __restrict__ W, __half* __restrict__ Wt,
                              int K, int N) {
    __shared__ float t[32][33];
    int kb = blockIdx.y * 32, nb = blockIdx.x * 32;
    for (int i = threadIdx.y; i < 32; i += 8)
        t[i][threadIdx.x] = W[(size_t)(kb + i) * N + nb + threadIdx.x];
    __syncthreads();
    for (int i = threadIdx.y; i < 32; i += 8)
        Wt[(size_t)(nb + i) * K + kb + threadIdx.x] = __float2half_rn(t[threadIdx.x][i]);
}

// ---------------- CSR build --------------------------------------------------
__global__ void zero_int_kernel(int* __restrict__ p, int n) {
    int i = blockIdx.x * blockDim.x + threadIdx.x;
    if (i < n) p[i] = 0;
}
__global__ void count_deg_kernel(const int* __restrict__ dst, int* __restrict__ deg, int E) {
    int e = blockIdx.x * blockDim.x + threadIdx.x;
    if (e < E) atomicAdd(&deg[dst[e]], 1);
}
__global__ __launch_bounds__(1024)
void scan_kernel(const int* __restrict__ deg, int* __restrict__ rowptr, int n) {
    __shared__ int sums[1024];
    const int chunk = (n + 1023) / 1024;
    const int start = threadIdx.x * chunk;
    int s = 0;
    for (int i = 0; i < chunk; i++) {
        int idx = start + i;
        s += (idx < n) ? deg[idx] : 0;
    }
    sums[threadIdx.x] = s;
    __syncthreads();
    for (int off = 1; off < 1024; off <<= 1) {
        int v = 0;
        if (threadIdx.x >= off) v = sums[threadIdx.x - off];
        __syncthreads();
        if (threadIdx.x >= off) sums[threadIdx.x] += v;
        __syncthreads();
    }
    int base = (threadIdx.x == 0) ? 0 : sums[threadIdx.x - 1];
    for (int i = 0; i < chunk; i++) {
        int idx = start + i;
        if (idx < n) { rowptr[idx] = base; base += deg[idx]; }
    }
    if (threadIdx.x == 1023) rowptr[n] = sums[1023];
}
__global__ void copy_cursor_kernel(const int* __restrict__ rowptr, int* __restrict__ cursor, int n) {
    int i = blockIdx.x * blockDim.x + threadIdx.x;
    if (i < n) cursor[i] = rowptr[i];
}
__global__ void scatter_kernel(const int* __restrict__ src, const int* __restrict__ dst,
                               int* __restrict__ cursor, int* __restrict__ csrc, int E) {
    int e = blockIdx.x * blockDim.x + threadIdx.x;
    if (e < E) {
        int p = atomicAdd(&cursor[dst[e]], 1);
        csrc[p] = src[e];
    }
}

// ---------------- per-node attention dot products (vectorized) --------------
__global__ void attn64_kernel(const __half* __restrict__ h,
                              const float* __restrict__ att_s,
                              const float* __restrict__ att_d,
                              float* __restrict__ asrc, float* __restrict__ adst, int n) {
    int node = (blockIdx.x * blockDim.x + threadIdx.x) >> 5;
    int lane = threadIdx.x & 31;
    if (node >= n) return;
    int fbase = lane * 8;
    uint4 u = reinterpret_cast<const uint4*>(h + (size_t)node * 256)[lane];
    float f[8];
    unpack8(u, f);
    float4 s0 = *reinterpret_cast<const float4*>(att_s + fbase);
    float4 s1 = *reinterpret_cast<const float4*>(att_s + fbase + 4);
    float4 d0 = *reinterpret_cast<const float4*>(att_d + fbase);
    float4 d1 = *reinterpret_cast<const float4*>(att_d + fbase + 4);
    float p1 = f[0]*s0.x + f[1]*s0.y + f[2]*s0.z + f[3]*s0.w
             + f[4]*s1.x + f[5]*s1.y + f[6]*s1.z + f[7]*s1.w;
    float p2 = f[0]*d0.x + f[1]*d0.y + f[2]*d0.z + f[3]*d0.w
             + f[4]*d1.x + f[5]*d1.y + f[6]*d1.z + f[7]*d1.w;
#pragma unroll
    for (int o = 4; o >= 1; o >>= 1) {
        p1 += __shfl_xor_sync(0xffffffffu, p1, o);
        p2 += __shfl_xor_sync(0xffffffffu, p2, o);
    }
    if ((lane & 7) == 0) {
        int head = lane >> 3;
        asrc[node * 4 + head] = p1;
        adst[node * 4 + head] = p2;
    }
}

__global__ void attn128_kernel(const __half* __restrict__ h,
                               const float* __restrict__ att_s,
                               const float* __restrict__ att_d,
                               float* __restrict__ asrc, float* __restrict__ adst, int n) {
    int node = (blockIdx.x * blockDim.x + threadIdx.x) >> 5;
    int lane = threadIdx.x & 31;
    if (node >= n) return;
    const uint4* hs = reinterpret_cast<const uint4*>(h + (size_t)node * 512);
    uint4 u0 = hs[lane];
    uint4 u1 = hs[32 + lane];
    float f0[8], f1[8];
    unpack8(u0, f0);
    unpack8(u1, f1);
    int fb0 = lane * 8, fb1 = 256 + lane * 8;
    float p1a, p2a, p1b, p2b;
    {
        float4 s0 = *reinterpret_cast<const float4*>(att_s + fb0);
        float4 s1 = *reinterpret_cast<const float4*>(att_s + fb0 + 4);
        float4 d0 = *reinterpret_cast<const float4*>(att_d + fb0);
        float4 d1 = *reinterpret_cast<const float4*>(att_d + fb0 + 4);
        p1a = f0[0]*s0.x + f0[1]*s0.y + f0[2]*s0.z + f0[3]*s0.w
            + f0[4]*s1.x + f0[5]*s1.y + f0[6]*s1.z + f0[7]*s1.w;
        p2a = f0[0]*d0.x + f0[1]*d0.y + f0[2]*d0.z + f0[3]*d0.w
            + f0[4]*d1.x + f0[5]*d1.y + f0[6]*d1.z + f0[7]*d1.w;
    }
    {
        float4 s0 = *reinterpret_cast<const float4*>(att_s + fb1);
        float4 s1 = *reinterpret_cast<const float4*>(att_s + fb1 + 4);
        float4 d0 = *reinterpret_cast<const float4*>(att_d + fb1);
        float4 d1 = *reinterpret_cast<const float4*>(att_d + fb1 + 4);
        p1b = f1[0]*s0.x + f1[1]*s0.y + f1[2]*s0.z + f1[3]*s0.w
            + f1[4]*s1.x + f1[5]*s1.y + f1[6]*s1.z + f1[7]*s1.w;
        p2b = f1[0]*d0.x + f1[1]*d0.y + f1[2]*d0.z + f1[3]*d0.w
            + f1[4]*d1.x + f1[5]*d1.y + f1[6]*d1.z + f1[7]*d1.w;
    }
#pragma unroll
    for (int o = 8; o >= 1; o >>= 1) {
        p1a += __shfl_xor_sync(0xffffffffu, p1a, o);
        p2a += __shfl_xor_sync(0xffffffffu, p2a, o);
        p1b += __shfl_xor_sync(0xffffffffu, p1b, o);
        p2b += __shfl_xor_sync(0xffffffffu, p2b, o);
    }
    if ((lane & 15) == 0) {
        int head = lane >> 4;
        asrc[node * 4 + head] = p1a;
        asrc[node * 4 + 2 + head] = p1b;
        adst[node * 4 + head] = p2a;
        adst[node * 4 + 2 + head] = p2b;
    }
}

// ---------------- fused score + CSR pull + denom + finalize ------------------
// One warp per node. Per edge: gather asrc4[csrc[i]] (parallel with h gather),
// w = exp(leakyrelu(asrc + adst[node])) — no max-shift (identical softmax).
// Depth-2 pipeline: csrc/asrc/h for edge i+1 issued before consuming edge i.

__global__ __launch_bounds__(256)
void agg_fin_concat(const int* __restrict__ rowptr, const int* __restrict__ csrc,
                    const float* __restrict__ asrc, const float* __restrict__ adst,
                    const __half* __restrict__ h,
                    const float* __restrict__ b, const float* __restrict__ lb,
                    const float* __restrict__ lin, __half* __restrict__ out, int n) {
    const int node = blockIdx.x * 8 + (threadIdx.x >> 5);
    if (node >= n) return;
    const int lane = threadIdx.x & 31;
    const int beg = rowptr[node], end = rowptr[node + 1];

    float4 ad = *reinterpret_cast<const float4*>(adst + (size_t)node * 4);

    float acc[8];
#pragma unroll
    for (int k = 0; k < 8; k++) acc[k] = 0.f;
    float4 ds = make_float4(0.f, 0.f, 0.f, 0.f);

    float4 sa_n = make_float4(0.f, 0.f, 0.f, 0.f);
    uint4  u_n  = make_uint4(0, 0, 0, 0);
    if (beg < end) {
        int s = csrc[beg];
        sa_n = *reinterpret_cast<const float4*>(asrc + (size_t)s * 4);
        u_n  = reinterpret_cast<const uint4*>(h + (size_t)s * 256)[lane];
    }
    for (int i = beg; i < end; i++) {
        float4 sa = sa_n;
        uint4  u  = u_n;
        if (i + 1 < end) {
            int s = csrc[i + 1];
            sa_n = *reinterpret_cast<const float4*>(asrc + (size_t)s * 4);
            u_n  = reinterpret_cast<const uint4*>(h + (size_t)s * 256)[lane];
        }
        float4 w4 = edge_w(sa, ad);
        float f[8];
        unpack8(u, f);
        float ws = (lane & 8) ? ((lane & 16) ? w4.w : w4.y)
                              : ((lane & 16) ? w4.z : w4.x);
#pragma unroll
        for (int k = 0; k < 8; k++) acc[k] += ws * f[k];
        ds.x += w4.x; ds.y += w4.y; ds.z += w4.z; ds.w += w4.w;
    }
    float dh = (lane & 8) ? ((lane & 16) ? ds.w : ds.y)
                          : ((lane & 16) ? ds.z : ds.x);
    float inv = 1.f / (dh + 1e-16f);

    const float4* b4   = reinterpret_cast<const float4*>(b);
    const float4* lb4  = reinterpret_cast<const float4*>(lb);
    const float4* lin4 = reinterpret_cast<const float4*>(lin + (size_t)node * 256);
    float4 bb0 = b4[lane * 2], bb1 = b4[lane * 2 + 1];
    float4 lbb0 = lb4[lane * 2], lbb1 = lb4[lane * 2 + 1];
    float4 ll0 = lin4[lane * 2], ll1 = lin4[lane * 2 + 1];
    float r[8];
    r[0] = acc[0] * inv + bb0.x + ll0.x + lbb0.x;
    r[1] = acc[1] * inv + bb0.y + ll0.y + lbb0.y;
    r[2] = acc[2] * inv + bb0.z + ll0.z + lbb0.z;
    r[3] = acc[3] * inv + bb0.w + ll0.w + lbb0.w;
    r[4] = acc[4] * inv + bb1.x + ll1.x + lbb1.x;
    r[5] = acc[5] * inv + bb1.y + ll1.y + lbb1.y;
    r[6] = acc[6] * inv + bb1.z + ll1.z + lbb1.z;
    r[7] = acc[7] * inv + bb1.w + ll1.w + lbb1.w;
#pragma unroll
    for (int k = 0; k < 8; k++) r[k] = r[k] > 0.f ? r[k] : expm1f(r[k]);
    uint4 o;
    __half2 hh;
    hh = __floats2half2_rn(r[0], r[1]); o.x = *reinterpret_cast<uint32_t*>(&hh);
    hh = __floats2half2_rn(r[2], r[3]); o.y = *reinterpret_cast<uint32_t*>(&hh);
    hh = __floats2half2_rn(r[4], r[5]); o.z = *reinterpret_cast<uint32_t*>(&hh);
    hh = __floats2half2_rn(r[6], r[7]); o.w = *reinterpret_cast<uint32_t*>(&hh);
    reinterpret_cast<uint4*>(out + (size_t)node * 256)[lane] = o;
}

__global__ __launch_bounds__(256)
void agg_fin_mean(const int* __restrict__ rowptr, const int* __restrict__ csrc,
                  const float* __restrict__ asrc, const float* __restrict__ adst,
                  const __half* __restrict__ h,
                  const float* __restrict__ b, const float* __restrict__ lb,
                  const float* __restrict__ lin, float* __restrict__ out, int n) {
    const int node = blockIdx.x * 8 + (threadIdx.x >> 5);
    if (node >= n) return;
    const int lane = threadIdx.x & 31;
    const int beg = rowptr[node], end = rowptr[node + 1];
    const bool hi = (lane & 16) != 0;

    float4 ad = *reinterpret_cast<const float4*>(adst + (size_t)node * 4);

    float acc0[8], acc1[8];
#pragma unroll
    for (int k = 0; k < 8; k++) { acc0[k] = 0.f; acc1[k] = 0.f; }
    float4 ds = make_float4(0.f, 0.f, 0.f, 0.f);

    float4 sa_n = make_float4(0.f, 0.f, 0.f, 0.f);
    uint4  u0_n = make_uint4(0, 0, 0, 0);
    uint4  u1_n = make_uint4(0, 0, 0, 0);
    if (beg < end) {
        int s = csrc[beg];
        sa_n = *reinterpret_cast<const float4*>(asrc + (size_t)s * 4);
        const uint4* hs = reinterpret_cast<const uint4*>(h + (size_t)s * 512);
        u0_n = hs[lane];
        u1_n = hs[32 + lane];
    }
    for (int i = beg; i < end; i++) {
        float4 sa = sa_n;
        uint4 u0 = u0_n, u1 = u1_n;
        if (i + 1 < end) {
            int s = csrc[i + 1];
            sa_n = *reinterpret_cast<const float4*>(asrc + (size_t)s * 4);
            const uint4* hs = reinterpret_cast<const uint4*>(h + (size_t)s * 512);
            u0_n = hs[lane];
            u1_n = hs[32 + lane];
        }
        float4 w4 = edge_w(sa, ad);
        float f0[8], f1[8];
        unpack8(u0, f0);
        unpack8(u1, f1);
        float w0 = hi ? w4.y : w4.x;
        float w1 = hi ? w4.w : w4.z;
#pragma unroll
        for (int k = 0; k < 8; k++) { acc0[k] += w0 * f0[k]; acc1[k] += w1 * f1[k]; }
        ds.x += w4.x; ds.y += w4.y; ds.z += w4.z; ds.w += w4.w;
    }
    float inv0 = 1.f / ((hi ? ds.y : ds.x) + 1e-16f);
    float inv1 = 1.f / ((hi ? ds.w : ds.z) + 1e-16f);

    float t[8];
#pragma unroll
    for (int k = 0; k < 8; k++) {
        t[k] = acc0[k] * inv0 + acc1[k] * inv1;
        t[k] += __shfl_xor_sync(0xffffffffu, t[k], 16);
    }
    if (lane < 16) {
        int fbase = lane * 8;
        const float4* b4   = reinterpret_cast<const float4*>(b + fbase);
        const float4* lb4  = reinterpret_cast<const float4*>(lb + fbase);
        const float4* lin4 = reinterpret_cast<const float4*>(lin + (size_t)node * 128 + fbase);
        float4 bb0 = b4[0], bb1 = b4[1];
        float4 lbb0 = lb4[0], lbb1 = lb4[1];
        float4 ll0 = lin4[0], ll1 = lin4[1];
        float4 r0, r1;
        r0.x = 0.25f * t[0] + bb0.x + ll0.x + lbb0.x;
        r0.y = 0.25f * t[1] + bb0.y + ll0.y + lbb0.y;
        r0.z = 0.25f * t[2] + bb0.z + ll0.z + lbb0.z;
        r0.w = 0.25f * t[3] + bb0.w + ll0.w + lbb0.w;
        r1.x = 0.25f * t[4] + bb1.x + ll1.x + lbb1.x;
        r1.y = 0.25f * t[5] + bb1.y + ll1.y + lbb1.y;
        r1.z = 0.25f * t[6] + bb1.z + ll1.z + lbb1.z;
        r1.w = 0.25f * t[7] + bb1.w + ll1.w + lbb1.w;
        float4* o4 = reinterpret_cast<float4*>(out + (size_t)node * 128 + fbase);
        o4[0] = r0;
        o4[1] = r1;
    }
}

// ---------------- host side --------------------------------------------------
extern "C" void kernel_launch(void* const* d_in, const int* in_sizes, int n_in,
                              void* d_out, int out_size) {
    const float* x  = (const float*)d_in[0];
    const int*   ei = (const int*)d_in[1];
    const int n = in_sizes[0] / 256;   // 50000
    const int E = in_sizes[1] / 2;     // 300000
    const int* src = ei;
    const int* dst = ei + E;

    cudaFuncSetAttribute(gemm_mma, cudaFuncAttributeMaxDynamicSharedMemorySize, GM_SMEM);

    float *linbuf, *asrcb, *adstb;
    __half *hbuf, *xhbuf, *b0buf, *b1buf, *wt;
    int *deg, *rowptr, *cursor, *csrc;
    cudaGetSymbolAddress((void**)&hbuf, g_h);
    cudaGetSymbolAddress((void**)&linbuf, g_lin);
    cudaGetSymbolAddress((void**)&xhbuf, g_xh);
    cudaGetSymbolAddress((void**)&b0buf, g_buf0);
    cudaGetSymbolAddress((void**)&b1buf, g_buf1);
    cudaGetSymbolAddress((void**)&asrcb, g_asrc);
    cudaGetSymbolAddress((void**)&adstb, g_adst);
    cudaGetSymbolAddress((void**)&deg, g_deg);
    cudaGetSymbolAddress((void**)&rowptr, g_rowptr);
    cudaGetSymbolAddress((void**)&cursor, g_cursor);
    cudaGetSymbolAddress((void**)&csrc, g_csrc);
    cudaGetSymbolAddress((void**)&wt, g_wt);

    __half* wt0  = wt;
    __half* lwt0 = wt + 65536;
    __half* wt1  = wt + 131072;
    __half* lwt1 = wt + 196608;
    __half* wt2  = wt + 262144;
    __half* lwt2 = wt + 393216;

    const int gy = (n + 127) / 128;   // 391
    dim3 tb(32, 8);

    // ordered so the 4th launch (the ncu capture slot) is the big fused GEMM
    transpose_cvt<<<dim3(8, 8), tb>>>((const float*)d_in[2], wt0, 256, 256);
    transpose_cvt<<<dim3(8, 8), tb>>>((const float*)d_in[6], lwt0, 256, 256);
    cvt_x_kernel<<<(n * 32 + 255) / 256, 256>>>(x, xhbuf, n * 32);
    gemm_mma<<<dim3(4, gy), 128, GM_SMEM>>>(xhbuf, wt0, hbuf, linbuf, n, 256, 256, 256); // 4th
    zero_int_kernel<<<(n + 255) / 256, 256>>>(deg, n);
    count_deg_kernel<<<(E + 255) / 256, 256>>>(dst, deg, E);
    scan_kernel<<<1, 1024>>>(deg, rowptr, n);
    copy_cursor_kernel<<<(n + 255) / 256, 256>>>(rowptr, cursor, n);
    scatter_kernel<<<(E + 255) / 256, 256>>>(src, dst, cursor, csrc, E);
    transpose_cvt<<<dim3(8, 8), tb>>>((const float*)d_in[8], wt1, 256, 256);
    transpose_cvt<<<dim3(8, 8), tb>>>((const float*)d_in[12], lwt1, 256, 256);
    transpose_cvt<<<dim3(16, 8), tb>>>((const float*)d_in[14], wt2, 256, 512);
    transpose_cvt<<<dim3(4, 8), tb>>>((const float*)d_in[18], lwt2, 256, 128);

    // layer 0
    attn64_kernel<<<(n + 7) / 8, 256>>>(hbuf, (const float*)d_in[3], (const float*)d_in[4],
                                        asrcb, adstb, n);
    agg_fin_concat<<<(n + 7) / 8, 256>>>(rowptr, csrc, asrcb, adstb, hbuf,
                                         (const float*)d_in[5], (const float*)d_in[7],
                                         linbuf, b0buf, n);
    // layer 1
    gemm_mma<<<dim3(4, gy), 128, GM_SMEM>>>(b0buf, wt1, hbuf, linbuf, n, 256, 256, 256);
    attn64_kernel<<<(n + 7) / 8, 256>>>(hbuf, (const float*)d_in[9], (const float*)d_in[10],
                                        asrcb, adstb, n);
    agg_fin_concat<<<(n + 7) / 8, 256>>>(rowptr, csrc, asrcb, adstb, hbuf,
                                         (const float*)d_in[11], (const float*)d_in[13],
                                         linbuf, b1buf, n);
    // layer 2 (fused N = 512 + 128 = 640)
    gemm_mma<<<dim3(5, gy), 128, GM_SMEM>>>(b1buf, wt2, hbuf, linbuf, n, 512, 512, 128);
    attn128_kernel<<<(n + 7) / 8, 256>>>(hbuf, (const float*)d_in[15], (const float*)d_in[16],
                                         asrcb, adstb, n);
    agg_fin_mean<<<(n + 7) / 8, 256>>>(rowptr, csrc, asrcb, adstb, hbuf,
                                       (const float*)d_in[17], (const float*)d_in[19],
                                       linbuf, (float*)d_out, n);
}

// round 16
// speedup vs baseline: 1.0971x; 1.0971x over previous
#include <cuda_runtime.h>
#include <cuda_fp16.h>
#include <math.h>
#include <cstdint>

#define NN 50000
#define NE 300000
#define NPAD (NN + 128)

// ---------------- scratch (device globals; no runtime allocation) ----------
__device__ __half   g_h   [(size_t)NPAD * 512];   // fp16 GAT transform
__device__ float    g_lin [(size_t)NPAD * 256];   // fp32 linear residual
__device__ __half   g_xh  [(size_t)NN * 256];     // fp16 input x
__device__ __half   g_buf0[(size_t)NN * 256];     // fp16 layer outputs
__device__ __half   g_buf1[(size_t)NN * 256];
__device__ float    g_asrc[NN * 4];
__device__ float    g_adst[NN * 4];
__device__ float    g_cw  [NE * 4];
__device__ int      g_deg [NN];
__device__ int      g_rowptr[NN + 1];
__device__ int      g_cursor[NN];
__device__ int      g_csrc[NE];
__device__ int      g_cdst[NE];
__device__ __half   g_wt  [425984];               // transposed fp16 weights

// ---------------- helpers ---------------------------------------------------
__device__ __forceinline__ uint32_t smem_u32(const void* p) {
    uint32_t a;
    asm("{ .reg .u64 t; cvta.to.shared.u64 t, %1; cvt.u32.u64 %0, t; }" : "=r"(a) : "l"(p));
    return a;
}
__device__ __forceinline__ void ldsm_x4(uint32_t& r0, uint32_t& r1, uint32_t& r2,
                                        uint32_t& r3, uint32_t addr) {
    asm volatile("ldmatrix.sync.aligned.m8n8.x4.shared.b16 {%0,%1,%2,%3}, [%4];"
                 : "=r"(r0), "=r"(r1), "=r"(r2), "=r"(r3) : "r"(addr));
}
__device__ __forceinline__ void mma_f16(float* c, uint32_t a0, uint32_t a1,
                                        uint32_t a2, uint32_t a3,
                                        uint32_t b0, uint32_t b1) {
    asm volatile(
        "mma.sync.aligned.m16n8k16.row.col.f32.f16.f16.f32 "
        "{%0,%1,%2,%3}, {%4,%5,%6,%7}, {%8,%9}, {%0,%1,%2,%3};"
        : "+f"(c[0]), "+f"(c[1]), "+f"(c[2]), "+f"(c[3])
        : "r"(a0), "r"(a1), "r"(a2), "r"(a3), "r"(b0), "r"(b1));
}
__device__ __forceinline__ void unpack8(const uint4& u, float* f) {
    float2 p;
    p = __half22float2(*reinterpret_cast<const __half2*>(&u.x)); f[0] = p.x; f[1] = p.y;
    p = __half22float2(*reinterpret_cast<const __half2*>(&u.y)); f[2] = p.x; f[3] = p.y;
    p = __half22float2(*reinterpret_cast<const __half2*>(&u.z)); f[4] = p.x; f[5] = p.y;
    p = __half22float2(*reinterpret_cast<const __half2*>(&u.w)); f[6] = p.x; f[7] = p.y;
}

// ---------------- fp16 mma.sync GEMM (round-13, unchanged) ------------------
#define GM_SMEM 65536

__global__ __launch_bounds__(128, 2)
void gemm_mma(const __half* __restrict__ A, const __half* __restrict__ Bt,
              __half* __restrict__ C1, float* __restrict__ C2,
              int M, int split, int ld1, int ld2) {
    extern __shared__ char smc[];
    const int K = 256;
    const int tid = threadIdx.x, lane = tid & 31, warp = tid >> 5;
    const int wm = warp >> 1, wn = warp & 1;
    const int mBase = blockIdx.y * 128;
    const int nBase = blockIdx.x * 128;
    const bool toC1 = (nBase < split);
    const int cBase = toC1 ? nBase : (nBase - split);

    const uint32_t sbase = smem_u32(smc);

    float acc[4][8][4];
#pragma unroll
    for (int i = 0; i < 4; i++)
#pragma unroll
        for (int j = 0; j < 8; j++)
#pragma unroll
            for (int r = 0; r < 4; r++) acc[i][j][r] = 0.f;

    const int rowb = tid >> 3;
    const int unit = tid & 7;
    uint32_t dstOff[8];
#pragma unroll
    for (int l = 0; l < 8; l++) {
        int row = rowb + 16 * l;
        dstOff[l] = (uint32_t)(row * 128 + ((unit ^ (row & 7)) << 4));
    }

    const int g  = lane >> 3, iL = lane & 7;
    const int rA  = wm * 64 + iL + (g & 1) * 8;
    const int kA  = g >> 1;
    const int rB  = wn * 64 + iL + (g >> 1) * 8;
    const int kB  = g & 1;
    const int rA7 = rA & 7, rB7 = rB & 7;

    uint4 aH[8], bH[8];
    const uint4 z4 = make_uint4(0, 0, 0, 0);
#pragma unroll
    for (int l = 0; l < 8; l++) {
        int row = rowb + 16 * l;
        int gr = mBase + row;
        aH[l] = (gr < M) ? *reinterpret_cast<const uint4*>(A + (size_t)gr * K + unit * 8) : z4;
        bH[l] = *reinterpret_cast<const uint4*>(Bt + (size_t)(nBase + row) * K + unit * 8);
    }
#pragma unroll
    for (int l = 0; l < 8; l++) {
        *reinterpret_cast<uint4*>(smc + dstOff[l]) = aH[l];
        *reinterpret_cast<uint4*>(smc + 16384 + dstOff[l]) = bH[l];
    }
    __syncthreads();

    int buf = 0;
    for (int k0 = 64; k0 <= K; k0 += 64) {
        const bool more = (k0 < K);
        if (more) {
#pragma unroll
            for (int l = 0; l < 8; l++) {
                int row = rowb + 16 * l;
                int gr = mBase + row;
                aH[l] = (gr < M) ? *reinterpret_cast<const uint4*>(A + (size_t)gr * K + k0 + unit * 8) : z4;
                bH[l] = *reinterpret_cast<const uint4*>(Bt + (size_t)(nBase + row) * K + k0 + unit * 8);
            }
        }
        {
            const uint32_t aB = sbase + (uint32_t)buf * 32768u;
            const uint32_t bB = aB + 16384u;
#pragma unroll
            for (int kt = 0; kt < 4; kt++) {
                uint32_t a[4][4];
#pragma unroll
                for (int mt = 0; mt < 4; mt++) {
                    uint32_t addr = aB + (uint32_t)(rA + mt * 16) * 128u +
                                    (uint32_t)(((kt * 2 + kA) ^ rA7) << 4);
                    ldsm_x4(a[mt][0], a[mt][1], a[mt][2], a[mt][3], addr);
                }
#pragma unroll
                for (int np = 0; np < 4; np++) {
                    uint32_t b0, b1, b2, b3;
                    uint32_t addr = bB + (uint32_t)(rB + np * 16) * 128u +
                                    (uint32_t)(((kt * 2 + kB) ^ rB7) << 4);
                    ldsm_x4(b0, b1, b2, b3, addr);
#pragma unroll
                    for (int i = 0; i < 4; i++) {
                        mma_f16(acc[i][2 * np],     a[i][0], a[i][1], a[i][2], a[i][3], b0, b1);
                        mma_f16(acc[i][2 * np + 1], a[i][0], a[i][1], a[i][2], a[i][3], b2, b3);
                    }
                }
            }
        }
        if (more) {
            char* As = smc + (buf ^ 1) * 32768;
#pragma unroll
            for (int l = 0; l < 8; l++) {
                *reinterpret_cast<uint4*>(As + dstOff[l]) = aH[l];
                *reinterpret_cast<uint4*>(As + 16384 + dstOff[l]) = bH[l];
            }
            __syncthreads();
            buf ^= 1;
        }
    }

    if (toC1) {
#pragma unroll
        for (int i = 0; i < 4; i++) {
            int r0 = mBase + wm * 64 + i * 16 + (lane >> 2);
#pragma unroll
            for (int j = 0; j < 8; j++) {
                int cc = cBase + wn * 64 + j * 8 + (lane & 3) * 2;
                *reinterpret_cast<__half2*>(C1 + (size_t)r0 * ld1 + cc) =
                    __floats2half2_rn(acc[i][j][0], acc[i][j][1]);
                *reinterpret_cast<__half2*>(C1 + (size_t)(r0 + 8) * ld1 + cc) =
                    __floats2half2_rn(acc[i][j][2], acc[i][j][3]);
            }
        }
    } else {
#pragma unroll
        for (int i = 0; i < 4; i++) {
            int r0 = mBase + wm * 64 + i * 16 + (lane >> 2);
#pragma unroll
            for (int j = 0; j < 8; j++) {
                int cc = cBase + wn * 64 + j * 8 + (lane & 3) * 2;
                *reinterpret_cast<float2*>(C2 + (size_t)r0 * ld2 + cc) =
                    make_float2(acc[i][j][0], acc[i][j][1]);
                *reinterpret_cast<float2*>(C2 + (size_t)(r0 + 8) * ld2 + cc) =
                    make_float2(acc[i][j][2], acc[i][j][3]);
            }
        }
    }
}

// ---------------- converts ---------------------------------------------------
__global__ void cvt_x_kernel(const float* __restrict__ in, __half* __restrict__ out, int n8) {
    int i = blockIdx.x * blockDim.x + threadIdx.x;
    if (i >= n8) return;
    float4 a = reinterpret_cast<const float4*>(in)[i * 2];
    float4 b = reinterpret_cast<const float4*>(in)[i * 2 + 1];
    uint4 r;
    __half2 h;
    h = __floats2half2_rn(a.x, a.y); r.x = *reinterpret_cast<uint32_t*>(&h);
    h = __floats2half2_rn(a.z, a.w); r.y = *reinterpret_cast<uint32_t*>(&h);
    h = __floats2half2_rn(b.x, b.y); r.z = *reinterpret_cast<uint32_t*>(&h);
    h = __floats2half2_rn(b.z, b.w); r.w = *reinterpret_cast<uint32_t*>(&h);
    reinterpret_cast<uint4*>(out)[i] = r;
}

// all 6 weight transposes in ONE launch (z selects the matrix; K=256 for all)
__global__ void transpose_all(const float* __restrict__ W0, const float* __restrict__ W1,
                              const float* __restrict__ W2, const float* __restrict__ W3,
                              const float* __restrict__ W4, const float* __restrict__ W5,
                              __half* __restrict__ O0, __half* __restrict__ O1,
                              __half* __restrict__ O2, __half* __restrict__ O3,
                              __half* __restrict__ O4, __half* __restrict__ O5) {
    __shared__ float t[32][33];
    const float* W;
    __half* O;
    int N;
    switch (blockIdx.z) {
        case 0:  W = W0; O = O0; N = 256; break;
        case 1:  W = W1; O = O1; N = 256; break;
        case 2:  W = W2; O = O2; N = 256; break;
        case 3:  W = W3; O = O3; N = 256; break;
        case 4:  W = W4; O = O4; N = 512; break;
        default: W = W5; O = O5; N = 128; break;
    }
    const int K = 256;
    int nb = blockIdx.x * 32;
    if (nb >= N) return;
    int kb = blockIdx.y * 32;
    for (int i = threadIdx.y; i < 32; i += 8)
        t[i][threadIdx.x] = W[(size_t)(kb + i) * N + nb + threadIdx.x];
    __syncthreads();
    for (int i = threadIdx.y; i < 32; i += 8)
        O[(size_t)(nb + i) * K + kb + threadIdx.x] = __float2half_rn(t[threadIdx.x][i]);
}

// ---------------- CSR build --------------------------------------------------
__global__ void zero_int_kernel(int* __restrict__ p, int n) {
    int i = blockIdx.x * blockDim.x + threadIdx.x;
    if (i < n) p[i] = 0;
}
__global__ void count_deg_kernel(const int* __restrict__ dst, int* __restrict__ deg, int E) {
    int e = blockIdx.x * blockDim.x + threadIdx.x;
    if (e < E) atomicAdd(&deg[dst[e]], 1);
}
__global__ __launch_bounds__(1024)
void scan_kernel(const int* __restrict__ deg, int* __restrict__ rowptr, int n) {
    __shared__ int sums[1024];
    const int chunk = (n + 1023) / 1024;
    const int start = threadIdx.x * chunk;
    int s = 0;
    for (int i = 0; i < chunk; i++) {
        int idx = start + i;
        s += (idx < n) ? deg[idx] : 0;
    }
    sums[threadIdx.x] = s;
    __syncthreads();
    for (int off = 1; off < 1024; off <<= 1) {
        int v = 0;
        if (threadIdx.x >= off) v = sums[threadIdx.x - off];
        __syncthreads();
        if (threadIdx.x >= off) sums[threadIdx.x] += v;
        __syncthreads();
    }
    int base = (threadIdx.x == 0) ? 0 : sums[threadIdx.x - 1];
    for (int i = 0; i < chunk; i++) {
        int idx = start + i;
        if (idx < n) { rowptr[idx] = base; base += deg[idx]; }
    }
    if (threadIdx.x == 1023) rowptr[n] = sums[1023];
}
__global__ void copy_cursor_kernel(const int* __restrict__ rowptr, int* __restrict__ cursor, int n) {
    int i = blockIdx.x * blockDim.x + threadIdx.x;
    if (i < n) cursor[i] = rowptr[i];
}
__global__ void scatter_kernel(const int* __restrict__ src, const int* __restrict__ dst,
                               int* __restrict__ cursor, int* __restrict__ csrc,
                               int* __restrict__ cdst, int E) {
    int e = blockIdx.x * blockDim.x + threadIdx.x;
    if (e < E) {
        int d = dst[e];
        int p = atomicAdd(&cursor[d], 1);
        csrc[p] = src[e];
        cdst[p] = d;
    }
}

// ---------------- per-node attention dot products (vectorized) --------------
__global__ void attn64_kernel(const __half* __restrict__ h,
                              const float* __restrict__ att_s,
                              const float* __restrict__ att_d,
                              float* __restrict__ asrc, float* __restrict__ adst, int n) {
    int node = (blockIdx.x * blockDim.x + threadIdx.x) >> 5;
    int lane = threadIdx.x & 31;
    if (node >= n) return;
    int fbase = lane * 8;
    uint4 u = reinterpret_cast<const uint4*>(h + (size_t)node * 256)[lane];
    float f[8];
    unpack8(u, f);
    float4 s0 = *reinterpret_cast<const float4*>(att_s + fbase);
    float4 s1 = *reinterpret_cast<const float4*>(att_s + fbase + 4);
    float4 d0 = *reinterpret_cast<const float4*>(att_d + fbase);
    float4 d1 = *reinterpret_cast<const float4*>(att_d + fbase + 4);
    float p1 = f[0]*s0.x + f[1]*s0.y + f[2]*s0.z + f[3]*s0.w
             + f[4]*s1.x + f[5]*s1.y + f[6]*s1.z + f[7]*s1.w;
    float p2 = f[0]*d0.x + f[1]*d0.y + f[2]*d0.z + f[3]*d0.w
             + f[4]*d1.x + f[5]*d1.y + f[6]*d1.z + f[7]*d1.w;
#pragma unroll
    for (int o = 4; o >= 1; o >>= 1) {
        p1 += __shfl_xor_sync(0xffffffffu, p1, o);
        p2 += __shfl_xor_sync(0xffffffffu, p2, o);
    }
    if ((lane & 7) == 0) {
        int head = lane >> 3;
        asrc[node * 4 + head] = p1;
        adst[node * 4 + head] = p2;
    }
}

__global__ void attn128_kernel(const __half* __restrict__ h,
                               const float* __restrict__ att_s,
                               const float* __restrict__ att_d,
                               float* __restrict__ asrc, float* __restrict__ adst, int n) {
    int node = (blockIdx.x * blockDim.x + threadIdx.x) >> 5;
    int lane = threadIdx.x & 31;
    if (node >= n) return;
    const uint4* hs = reinterpret_cast<const uint4*>(h + (size_t)node * 512);
    uint4 u0 = hs[lane];
    uint4 u1 = hs[32 + lane];
    float f0[8], f1[8];
    unpack8(u0, f0);
    unpack8(u1, f1);
    int fb0 = lane * 8, fb1 = 256 + lane * 8;
    float p1a, p2a, p1b, p2b;
    {
        float4 s0 = *reinterpret_cast<const float4*>(att_s + fb0);
        float4 s1 = *reinterpret_cast<const float4*>(att_s + fb0 + 4);
        float4 d0 = *reinterpret_cast<const float4*>(att_d + fb0);
        float4 d1 = *reinterpret_cast<const float4*>(att_d + fb0 + 4);
        p1a = f0[0]*s0.x + f0[1]*s0.y + f0[2]*s0.z + f0[3]*s0.w
            + f0[4]*s1.x + f0[5]*s1.y + f0[6]*s1.z + f0[7]*s1.w;
        p2a = f0[0]*d0.x + f0[1]*d0.y + f0[2]*d0.z + f0[3]*d0.w
            + f0[4]*d1.x + f0[5]*d1.y + f0[6]*d1.z + f0[7]*d1.w;
    }
    {
        float4 s0 = *reinterpret_cast<const float4*>(att_s + fb1);
        float4 s1 = *reinterpret_cast<const float4*>(att_s + fb1 + 4);
        float4 d0 = *reinterpret_cast<const float4*>(att_d + fb1);
        float4 d1 = *reinterpret_cast<const float4*>(att_d + fb1 + 4);
        p1b = f1[0]*s0.x + f1[1]*s0.y + f1[2]*s0.z + f1[3]*s0.w
            + f1[4]*s1.x + f1[5]*s1.y + f1[6]*s1.z + f1[7]*s1.w;
        p2b = f1[0]*d0.x + f1[1]*d0.y + f1[2]*d0.z + f1[3]*d0.w
            + f1[4]*d1.x + f1[5]*d1.y + f1[6]*d1.z + f1[7]*d1.w;
    }
#pragma unroll
    for (int o = 8; o >= 1; o >>= 1) {
        p1a += __shfl_xor_sync(0xffffffffu, p1a, o);
        p2a += __shfl_xor_sync(0xffffffffu, p2a, o);
        p1b += __shfl_xor_sync(0xffffffffu, p1b, o);
        p2b += __shfl_xor_sync(0xffffffffu, p2b, o);
    }
    if ((lane & 15) == 0) {
        int head = lane >> 4;
        asrc[node * 4 + head] = p1a;
        asrc[node * 4 + 2 + head] = p1b;
        adst[node * 4 + head] = p2a;
        adst[node * 4 + 2 + head] = p2b;
    }
}

// ---------------- edge score: CSR-position indexed, sequential write ---------
// w = exp(leakyrelu(asrc[csrc[i]] + adst[cdst[i]])) — no max-shift (identical
// softmax; scores are O(10), far from fp32 overflow).
__global__ void edge_score_kernel(const int* __restrict__ csrc, const int* __restrict__ cdst,
                                  const float* __restrict__ asrc, const float* __restrict__ adst,
                                  float* __restrict__ cw, int E) {
    int i = blockIdx.x * blockDim.x + threadIdx.x;
    if (i >= E) return;
    int s = csrc[i], d = cdst[i];
    float4 a = *reinterpret_cast<const float4*>(asrc + s * 4);
    float4 b = *reinterpret_cast<const float4*>(adst + d * 4);
    float4 v;
    v.x = a.x + b.x; v.x = v.x > 0.f ? v.x : 0.2f * v.x;
    v.y = a.y + b.y; v.y = v.y > 0.f ? v.y : 0.2f * v.y;
    v.z = a.z + b.z; v.z = v.z > 0.f ? v.z : 0.2f * v.z;
    v.w = a.w + b.w; v.w = v.w > 0.f ? v.w : 0.2f * v.w;
    v.x = expf(v.x); v.y = expf(v.y); v.z = expf(v.z); v.w = expf(v.w);
    *reinterpret_cast<float4*>(cw + (size_t)i * 4) = v;
}

// ---------------- CSR pull + denom + finalize (round-14, unchanged) ----------
__global__ __launch_bounds__(256)
void agg_fin_concat(const int* __restrict__ rowptr, const int* __restrict__ csrc,
                    const float* __restrict__ cw, const __half* __restrict__ h,
                    const float* __restrict__ b, const float* __restrict__ lb,
                    const float* __restrict__ lin, __half* __restrict__ out, int n) {
    const int node = blockIdx.x * 8 + (threadIdx.x >> 5);
    if (node >= n) return;
    const int lane = threadIdx.x & 31;
    const int beg = rowptr[node], end = rowptr[node + 1];

    float acc[8];
#pragma unroll
    for (int k = 0; k < 8; k++) acc[k] = 0.f;
    float4 ds = make_float4(0.f, 0.f, 0.f, 0.f);

    int s_next = 0;
    float4 w_next = make_float4(0.f, 0.f, 0.f, 0.f);
    if (beg < end) {
        s_next = csrc[beg];
        w_next = *reinterpret_cast<const float4*>(cw + (size_t)beg * 4);
    }
    for (int i = beg; i < end; i++) {
        int s = s_next;
        float4 w4 = w_next;
        if (i + 1 < end) {
            s_next = csrc[i + 1];
            w_next = *reinterpret_cast<const float4*>(cw + (size_t)(i + 1) * 4);
        }
        uint4 u = reinterpret_cast<const uint4*>(h + (size_t)s * 256)[lane];
        float f[8];
        unpack8(u, f);
        float ws = (lane & 8) ? ((lane & 16) ? w4.w : w4.y)
                              : ((lane & 16) ? w4.z : w4.x);
#pragma unroll
        for (int k = 0; k < 8; k++) acc[k] += ws * f[k];
        ds.x += w4.x; ds.y += w4.y; ds.z += w4.z; ds.w += w4.w;
    }
    float dh = (lane & 8) ? ((lane & 16) ? ds.w : ds.y)
                          : ((lane & 16) ? ds.z : ds.x);
    float inv = 1.f / (dh + 1e-16f);

    const float4* b4   = reinterpret_cast<const float4*>(b);
    const float4* lb4  = reinterpret_cast<const float4*>(lb);
    const float4* lin4 = reinterpret_cast<const float4*>(lin + (size_t)node * 256);
    float4 bb0 = b4[lane * 2], bb1 = b4[lane * 2 + 1];
    float4 lbb0 = lb4[lane * 2], lbb1 = lb4[lane * 2 + 1];
    float4 ll0 = lin4[lane * 2], ll1 = lin4[lane * 2 + 1];
    float r[8];
    r[0] = acc[0] * inv + bb0.x + ll0.x + lbb0.x;
    r[1] = acc[1] * inv + bb0.y + ll0.y + lbb0.y;
    r[2] = acc[2] * inv + bb0.z + ll0.z + lbb0.z;
    r[3] = acc[3] * inv + bb0.w + ll0.w + lbb0.w;
    r[4] = acc[4] * inv + bb1.x + ll1.x + lbb1.x;
    r[5] = acc[5] * inv + bb1.y + ll1.y + lbb1.y;
    r[6] = acc[6] * inv + bb1.z + ll1.z + lbb1.z;
    r[7] = acc[7] * inv + bb1.w + ll1.w + lbb1.w;
#pragma unroll
    for (int k = 0; k < 8; k++) r[k] = r[k] > 0.f ? r[k] : expm1f(r[k]);
    uint4 o;
    __half2 hh;
    hh = __floats2half2_rn(r[0], r[1]); o.x = *reinterpret_cast<uint32_t*>(&hh);
    hh = __floats2half2_rn(r[2], r[3]); o.y = *reinterpret_cast<uint32_t*>(&hh);
    hh = __floats2half2_rn(r[4], r[5]); o.z = *reinterpret_cast<uint32_t*>(&hh);
    hh = __floats2half2_rn(r[6], r[7]); o.w = *reinterpret_cast<uint32_t*>(&hh);
    reinterpret_cast<uint4*>(out + (size_t)node * 256)[lane] = o;
}

__global__ __launch_bounds__(256)
void agg_fin_mean(const int* __restrict__ rowptr, const int* __restrict__ csrc,
                  const float* __restrict__ cw, const __half* __restrict__ h,
                  const float* __restrict__ b, const float* __restrict__ lb,
                  const float* __restrict__ lin, float* __restrict__ out, int n) {
    const int node = blockIdx.x * 8 + (threadIdx.x >> 5);
    if (node >= n) return;
    const int lane = threadIdx.x & 31;
    const int beg = rowptr[node], end = rowptr[node + 1];
    const bool hi = (lane & 16) != 0;

    float acc0[8], acc1[8];
#pragma unroll
    for (int k = 0; k < 8; k++) { acc0[k] = 0.f; acc1[k] = 0.f; }
    float4 ds = make_float4(0.f, 0.f, 0.f, 0.f);

    int s_next = 0;
    float4 w_next = make_float4(0.f, 0.f, 0.f, 0.f);
    if (beg < end) {
        s_next = csrc[beg];
        w_next = *reinterpret_cast<const float4*>(cw + (size_t)beg * 4);
    }
    for (int i = beg; i < end; i++) {
        int s = s_next;
        float4 w4 = w_next;
        if (i + 1 < end) {
            s_next = csrc[i + 1];
            w_next = *reinterpret_cast<const float4*>(cw + (size_t)(i + 1) * 4);
        }
        const uint4* hs = reinterpret_cast<const uint4*>(h + (size_t)s * 512);
        uint4 u0 = hs[lane];
        uint4 u1 = hs[32 + lane];
        float f0[8], f1[8];
        unpack8(u0, f0);
        unpack8(u1, f1);
        float w0 = hi ? w4.y : w4.x;
        float w1 = hi ? w4.w : w4.z;
#pragma unroll
        for (int k = 0; k < 8; k++) { acc0[k] += w0 * f0[k]; acc1[k] += w1 * f1[k]; }
        ds.x += w4.x; ds.y += w4.y; ds.z += w4.z; ds.w += w4.w;
    }
    float inv0 = 1.f / ((hi ? ds.y : ds.x) + 1e-16f);
    float inv1 = 1.f / ((hi ? ds.w : ds.z) + 1e-16f);

    float t[8];
#pragma unroll
    for (int k = 0; k < 8; k++) {
        t[k] = acc0[k] * inv0 + acc1[k] * inv1;
        t[k] += __shfl_xor_sync(0xffffffffu, t[k], 16);
    }
    if (lane < 16) {
        int fbase = lane * 8;
        const float4* b4   = reinterpret_cast<const float4*>(b + fbase);
        const float4* lb4  = reinterpret_cast<const float4*>(lb + fbase);
        const float4* lin4 = reinterpret_cast<const float4*>(lin + (size_t)node * 128 + fbase);
        float4 bb0 = b4[0], bb1 = b4[1];
        float4 lbb0 = lb4[0], lbb1 = lb4[1];
        float4 ll0 = lin4[0], ll1 = lin4[1];
        float4 r0, r1;
        r0.x = 0.25f * t[0] + bb0.x + ll0.x + lbb0.x;
        r0.y = 0.25f * t[1] + bb0.y + ll0.y + lbb0.y;
        r0.z = 0.25f * t[2] + bb0.z + ll0.z + lbb0.z;
        r0.w = 0.25f * t[3] + bb0.w + ll0.w + lbb0.w;
        r1.x = 0.25f * t[4] + bb1.x + ll1.x + lbb1.x;
        r1.y = 0.25f * t[5] + bb1.y + ll1.y + lbb1.y;
        r1.z = 0.25f * t[6] + bb1.z + ll1.z + lbb1.z;
        r1.w = 0.25f * t[7] + bb1.w + ll1.w + lbb1.w;
        float4* o4 = reinterpret_cast<float4*>(out + (size_t)node * 128 + fbase);
        o4[0] = r0;
        o4[1] = r1;
    }
}

// ---------------- host side --------------------------------------------------
extern "C" void kernel_launch(void* const* d_in, const int* in_sizes, int n_in,
                              void* d_out, int out_size) {
    const float* x  = (const float*)d_in[0];
    const int*   ei = (const int*)d_in[1];
    const int n = in_sizes[0] / 256;   // 50000
    const int E = in_sizes[1] / 2;     // 300000
    const int* src = ei;
    const int* dst = ei + E;

    cudaFuncSetAttribute(gemm_mma, cudaFuncAttributeMaxDynamicSharedMemorySize, GM_SMEM);

    float *linbuf, *asrcb, *adstb, *cwb;
    __half *hbuf, *xhbuf, *b0buf, *b1buf, *wt;
    int *deg, *rowptr, *cursor, *csrc, *cdst;
    cudaGetSymbolAddress((void**)&hbuf, g_h);
    cudaGetSymbolAddress((void**)&linbuf, g_lin);
    cudaGetSymbolAddress((void**)&xhbuf, g_xh);
    cudaGetSymbolAddress((void**)&b0buf, g_buf0);
    cudaGetSymbolAddress((void**)&b1buf, g_buf1);
    cudaGetSymbolAddress((void**)&asrcb, g_asrc);
    cudaGetSymbolAddress((void**)&adstb, g_adst);
    cudaGetSymbolAddress((void**)&cwb, g_cw);
    cudaGetSymbolAddress((void**)&deg, g_deg);
    cudaGetSymbolAddress((void**)&rowptr, g_rowptr);
    cudaGetSymbolAddress((void**)&cursor, g_cursor);
    cudaGetSymbolAddress((void**)&csrc, g_csrc);
    cudaGetSymbolAddress((void**)&cdst, g_cdst);
    cudaGetSymbolAddress((void**)&wt, g_wt);

    __half* wt0  = wt;
    __half* lwt0 = wt + 65536;
    __half* wt1  = wt + 131072;
    __half* lwt1 = wt + 196608;
    __half* wt2  = wt + 262144;
    __half* lwt2 = wt + 393216;

    const int gy = (n + 127) / 128;   // 391
    dim3 tb(32, 8);

    // ordered so the 4th launch (the ncu capture slot) is the big fused GEMM
    transpose_all<<<dim3(16, 8, 6), tb>>>(
        (const float*)d_in[2], (const float*)d_in[6], (const float*)d_in[8],
        (const float*)d_in[12], (const float*)d_in[14], (const float*)d_in[18],
        wt0, lwt0, wt1, lwt1, wt2, lwt2);
    cvt_x_kernel<<<(n * 32 + 255) / 256, 256>>>(x, xhbuf, n * 32);
    zero_int_kernel<<<(n + 255) / 256, 256>>>(deg, n);
    gemm_mma<<<dim3(4, gy), 128, GM_SMEM>>>(xhbuf, wt0, hbuf, linbuf, n, 256, 256, 256); // 4th
    count_deg_kernel<<<(E + 255) / 256, 256>>>(dst, deg, E);
    scan_kernel<<<1, 1024>>>(deg, rowptr, n);
    copy_cursor_kernel<<<(n + 255) / 256, 256>>>(rowptr, cursor, n);
    scatter_kernel<<<(E + 255) / 256, 256>>>(src, dst, cursor, csrc, cdst, E);

    // layer 0
    attn64_kernel<<<(n + 7) / 8, 256>>>(hbuf, (const float*)d_in[3], (const float*)d_in[4],
                                        asrcb, adstb, n);
    edge_score_kernel<<<(E + 255) / 256, 256>>>(csrc, cdst, asrcb, adstb, cwb, E);
    agg_fin_concat<<<(n + 7) / 8, 256>>>(rowptr, csrc, cwb, hbuf,
                                         (const float*)d_in[5], (const float*)d_in[7],
                                         linbuf, b0buf, n);
    // layer 1
    gemm_mma<<<dim3(4, gy), 128, GM_SMEM>>>(b0buf, wt1, hbuf, linbuf, n, 256, 256, 256);
    attn64_kernel<<<(n + 7) / 8, 256>>>(hbuf, (const float*)d_in[9], (const float*)d_in[10],
                                        asrcb, adstb, n);
    edge_score_kernel<<<(E + 255) / 256, 256>>>(csrc, cdst, asrcb, adstb, cwb, E);
    agg_fin_concat<<<(n + 7) / 8, 256>>>(rowptr, csrc, cwb, hbuf,
                                         (const float*)d_in[11], (const float*)d_in[13],
                                         linbuf, b1buf, n);
    // layer 2 (fused N = 512 + 128 = 640)
    gemm_mma<<<dim3(5, gy), 128, GM_SMEM>>>(b1buf, wt2, hbuf, linbuf, n, 512, 512, 128);
    attn128_kernel<<<(n + 7) / 8, 256>>>(hbuf, (const float*)d_in[15], (const float*)d_in[16],
                                         asrcb, adstb, n);
    edge_score_kernel<<<(E + 255) / 256, 256>>>(csrc, cdst, asrcb, adstb, cwb, E);
    agg_fin_mean<<<(n + 7) / 8, 256>>>(rowptr, csrc, cwb, hbuf,
                                       (const float*)d_in[17], (const float*)d_in[19],
                                       linbuf, (float*)d_out, n);
}